// round 16
// baseline (speedup 1.0000x reference)
#include <cuda_runtime.h>

// 2-layer GCN, N=100000 nodes, E=1200000 edges, D=64.
//   per layer: xw = X@W ; agg = segment_sum(xw[src] -> dst) ;
//              h = relu(agg + b) + relu(X@Wr + br)
//
// R13: revert to R11 atomic-scatter plan (CSR build per replay was a net
// loss), keep the packed fma.rn.f32x2 GEMM inner loop from R12.
//
// Launch plan (default stream, graph-capturable, allocation-free):
//   L1: gemm<MODE0>(feats,W1)  -> g_xw, zero g_agg
//       scatter(src,dst)       -> g_agg += g_xw[src]  (red.global.add.v4.f32)
//       gemm<MODE1>(feats,Wr1) -> g_h1 = relu(g_agg+b1) + relu(feats@Wr1+br1)
//   L2: same with g_h1 as input, output to d_out.

static constexpr int NN = 100000;
static constexpr int EE = 1200000;

// Scratch (device globals; allocation-free). 16B-aligned for float4/red.v4.
__device__ __align__(16) float g_xw [NN * 64];
__device__ __align__(16) float g_agg[NN * 64];
__device__ __align__(16) float g_h1 [NN * 64];

// ============================== GEMM ==============================

__device__ __forceinline__ unsigned long long fma2(unsigned long long a,
                                                   unsigned long long b,
                                                   unsigned long long c) {
    unsigned long long d;
    asm("fma.rn.f32x2 %0, %1, %2, %3;" : "=l"(d) : "l"(a), "l"(b), "l"(c));
    return d;
}

// XOR-swizzled transposed X tile index: element (k, r) of XsT[64][64] at
//   k*64 + (((r>>2) ^ ((k>>2)&15)) * 4 + (r&3))
// -> transpose stores ~2-way conflicted, compute reads are broadcast LDS.128.
__device__ __forceinline__ int swidx(int k, int r) {
    return (k << 6) + (((((r >> 2) ^ ((k >> 2) & 15))) << 2) | (r & 3));
}

// MODE 0: g_xw = X @ W ; also zero g_agg rows (scatter accumulates into it).
// MODE 1: Y = relu(X @ W + bias_r) + relu(g_agg + bias_a)
// XH1: X comes from g_h1. YH1: Y goes to g_h1.
template<int MODE, bool XH1, bool YH1>
__global__ __launch_bounds__(256)
void gemm64_k(const float* __restrict__ Xp,
              const float* __restrict__ W,
              const float* __restrict__ bias_r,
              const float* __restrict__ bias_a,
              float* __restrict__ Yp,
              int n)
{
    __shared__ __align__(16) float XsT[64 * 64];   // transposed + swizzled
    __shared__ __align__(16) float Ws [64 * 64];   // row-major Ws[k*64+j]

    const float* X = XH1 ? (const float*)g_h1 : Xp;
    float*       Y = YH1 ? (float*)g_h1       : Yp;

    const int tid  = threadIdx.x;
    const int row0 = blockIdx.x << 6;

    // Stage W (4096 floats = 1024 float4)
    const float4* W4 = (const float4*)W;
    float4* Ws4 = (float4*)Ws;
#pragma unroll
    for (int i = 0; i < 4; ++i) Ws4[tid + i * 256] = W4[tid + i * 256];

    // Stage X tile transposed+swizzled
    const float4* X4 = (const float4*)X;
#pragma unroll
    for (int i = 0; i < 4; ++i) {
        int idx = tid + i * 256;
        int r   = idx >> 4;
        int c4  = idx & 15;
        int row = row0 + r;
        float4 v = make_float4(0.f, 0.f, 0.f, 0.f);
        if (row < n) v = X4[row * 16 + c4];
        int c = c4 << 2;
        XsT[swidx(c + 0, r)] = v.x;
        XsT[swidx(c + 1, r)] = v.y;
        XsT[swidx(c + 2, r)] = v.z;
        XsT[swidx(c + 3, r)] = v.w;
    }
    __syncthreads();

    const int j  = tid & 63;   // output column
    const int rg = tid >> 6;   // row group (16 rows)

    unsigned long long acc2[8];
#pragma unroll
    for (int p = 0; p < 8; ++p) acc2[p] = 0ull;

#pragma unroll 8
    for (int k = 0; k < 64; ++k) {
        float wv = Ws[(k << 6) + j];
        unsigned long long wv2;
        asm("mov.b64 %0, {%1, %1};" : "=l"(wv2) : "f"(wv));

        const ulonglong2* xk = (const ulonglong2*)(XsT + (k << 6));
        int sw = (k >> 2) & 15;
        ulonglong2 a0 = xk[((rg << 2) + 0) ^ sw];   // rows +0..3 (2 packed pairs)
        ulonglong2 a1 = xk[((rg << 2) + 1) ^ sw];   // rows +4..7
        ulonglong2 a2 = xk[((rg << 2) + 2) ^ sw];   // rows +8..11
        ulonglong2 a3 = xk[((rg << 2) + 3) ^ sw];   // rows +12..15

        acc2[0] = fma2(a0.x, wv2, acc2[0]);
        acc2[1] = fma2(a0.y, wv2, acc2[1]);
        acc2[2] = fma2(a1.x, wv2, acc2[2]);
        acc2[3] = fma2(a1.y, wv2, acc2[3]);
        acc2[4] = fma2(a2.x, wv2, acc2[4]);
        acc2[5] = fma2(a2.y, wv2, acc2[5]);
        acc2[6] = fma2(a3.x, wv2, acc2[6]);
        acc2[7] = fma2(a3.y, wv2, acc2[7]);
    }

    const int rbase = row0 + (rg << 4);
    if (MODE == 0) {
#pragma unroll
        for (int p = 0; p < 8; ++p) {
            float lo, hi;
            asm("mov.b64 {%0, %1}, %2;" : "=f"(lo), "=f"(hi) : "l"(acc2[p]));
            int r0 = rbase + 2 * p;
            if (r0 < n) {
                g_xw [(size_t)r0 * 64 + j] = lo;
                g_agg[(size_t)r0 * 64 + j] = 0.f;
            }
            if (r0 + 1 < n) {
                g_xw [(size_t)(r0 + 1) * 64 + j] = hi;
                g_agg[(size_t)(r0 + 1) * 64 + j] = 0.f;
            }
        }
    } else {
        float brj = bias_r[j];
        float baj = bias_a[j];
#pragma unroll
        for (int p = 0; p < 8; ++p) {
            float lo, hi;
            asm("mov.b64 {%0, %1}, %2;" : "=f"(lo), "=f"(hi) : "l"(acc2[p]));
            int r0 = rbase + 2 * p;
            if (r0 < n) {
                float conv = g_agg[(size_t)r0 * 64 + j] + baj;
                conv = conv > 0.f ? conv : 0.f;
                float res = lo + brj;
                res = res > 0.f ? res : 0.f;
                Y[(size_t)r0 * 64 + j] = conv + res;
            }
            if (r0 + 1 < n) {
                float conv = g_agg[(size_t)(r0 + 1) * 64 + j] + baj;
                conv = conv > 0.f ? conv : 0.f;
                float res = hi + brj;
                res = res > 0.f ? res : 0.f;
                Y[(size_t)(r0 + 1) * 64 + j] = conv + res;
            }
        }
    }
}

// ============================ scatter ============================
// Vectorized 16B float atomic add (sm_90+): 4 fp32 adds per L2 atomic op.
__device__ __forceinline__ void red_add_v4(float4* addr, float4 v) {
    asm volatile("red.global.add.v4.f32 [%0], {%1, %2, %3, %4};"
                 :: "l"(addr), "f"(v.x), "f"(v.y), "f"(v.z), "f"(v.w)
                 : "memory");
}

// One thread per (edge, float4-quad): 16 threads per edge, fully coalesced
// 256B gather per edge, 16B vector red per thread.
__global__ __launch_bounds__(256)
void scatter_k(const int* __restrict__ src, const int* __restrict__ dst)
{
    unsigned gid = blockIdx.x * 256u + threadIdx.x;   // EE*16 = 19.2M exact
    unsigned e = gid >> 4;
    unsigned q = gid & 15;
    int s = __ldg(src + e);
    int d = __ldg(dst + e);
    const float4* xw4 = (const float4*)g_xw;
    float4 v = __ldg(xw4 + (size_t)s * 16 + q);
    red_add_v4(((float4*)g_agg) + (size_t)d * 16 + q, v);
}

// ============================== launch ==============================

extern "C" void kernel_launch(void* const* d_in, const int* in_sizes, int n_in,
                              void* d_out, int out_size)
{
    const float* feats = (const float*)d_in[0];
    const float* W1    = (const float*)d_in[1];
    const float* b1    = (const float*)d_in[2];
    const float* Wr1   = (const float*)d_in[3];
    const float* br1   = (const float*)d_in[4];
    const float* W2    = (const float*)d_in[5];
    const float* b2    = (const float*)d_in[6];
    const float* Wr2   = (const float*)d_in[7];
    const float* br2   = (const float*)d_in[8];
    const int*   src   = (const int*)d_in[9];
    const int*   dst   = (const int*)d_in[10];
    float*       out   = (float*)d_out;

    const int GB = (NN + 63) >> 6;            // 1563 blocks
    const int SB = (EE * 16) / 256;           // 75000 blocks

    // ---- Layer 1 ----
    gemm64_k<0, false, false><<<GB, 256>>>(feats, W1, nullptr, nullptr, nullptr, NN);
    scatter_k<<<SB, 256>>>(src, dst);
    gemm64_k<1, false, true ><<<GB, 256>>>(feats, Wr1, br1, b1, nullptr, NN);

    // ---- Layer 2 ----
    gemm64_k<0, true,  false><<<GB, 256>>>(nullptr, W2, nullptr, nullptr, nullptr, NN);
    scatter_k<<<SB, 256>>>(src, dst);
    gemm64_k<1, true,  false><<<GB, 256>>>(nullptr, Wr2, br2, b2, out, NN);
}

// round 17
// speedup vs baseline: 1.2419x; 1.2419x over previous
#include <cuda_runtime.h>

// 2-layer GCN, N=100000 nodes, E=1200000 edges, D=64.
//   per layer: xw = X@W ; agg = segment_sum(xw[src] -> dst) ;
//              h = relu(agg + b) + relu(X@Wr + br)
//
// R16: GEMM was L1/smem-wavefront bound (L1=78.5%, fma=32.5%). Re-tile to
// 4x4 register blocking: per k, 1 LDS.128 (A rows, pre-packed f32x2 pairs)
// + 1 LDS.128 (W cols) for 16 FMAs (8 FFMA2), and a fully vectorized
// STG.128/LDG.128 epilogue. Scatter stays red.global.add.v4.f32 (measured
// at its L2-atomic floor in R12).

static constexpr int NN = 100000;
static constexpr int EE = 1200000;

// Scratch (device globals; allocation-free). 16B-aligned for float4/red.v4.
__device__ __align__(16) float g_xw [NN * 64];
__device__ __align__(16) float g_agg[NN * 64];
__device__ __align__(16) float g_h1 [NN * 64];

// ============================== GEMM ==============================

__device__ __forceinline__ unsigned long long fma2(unsigned long long a,
                                                   unsigned long long b,
                                                   unsigned long long c) {
    unsigned long long d;
    asm("fma.rn.f32x2 %0, %1, %2, %3;" : "=l"(d) : "l"(a), "l"(b), "l"(c));
    return d;
}

__device__ __forceinline__ unsigned long long dup2(float v) {
    unsigned long long d;
    asm("mov.b64 %0, {%1, %1};" : "=l"(d) : "f"(v));
    return d;
}

// XOR-swizzled transposed X tile: element (k, r) of XsT[64][64] lives at
//   k*64 + (((r>>2) ^ ((k>>2)&15)) * 4 + (r&3))
// -> for fixed k, rows 4t..4t+3 are one contiguous float4 at chunk (t ^ sw).
__device__ __forceinline__ int swidx(int k, int r) {
    return (k << 6) + (((((r >> 2) ^ ((k >> 2) & 15))) << 2) | (r & 3));
}

// MODE 0: g_xw = X @ W ; also zero g_agg rows (scatter accumulates into it).
// MODE 1: Y = relu(X @ W + bias_r) + relu(g_agg + bias_a)
// XH1: X comes from g_h1. YH1: Y goes to g_h1.
template<int MODE, bool XH1, bool YH1>
__global__ __launch_bounds__(256)
void gemm64_k(const float* __restrict__ Xp,
              const float* __restrict__ W,
              const float* __restrict__ bias_r,
              const float* __restrict__ bias_a,
              float* __restrict__ Yp,
              int n)
{
    __shared__ __align__(16) float XsT[64 * 64];   // transposed + swizzled
    __shared__ __align__(16) float Ws [64 * 64];   // row-major Ws[k*64+j]

    const float* X = XH1 ? (const float*)g_h1 : Xp;
    float*       Y = YH1 ? (float*)g_h1       : Yp;

    const int tid  = threadIdx.x;
    const int row0 = blockIdx.x << 6;

    // Stage W (4096 floats = 1024 float4)
    const float4* W4 = (const float4*)W;
    float4* Ws4 = (float4*)Ws;
#pragma unroll
    for (int i = 0; i < 4; ++i) Ws4[tid + i * 256] = W4[tid + i * 256];

    // Stage X tile transposed+swizzled
    const float4* X4 = (const float4*)X;
#pragma unroll
    for (int i = 0; i < 4; ++i) {
        int idx = tid + i * 256;
        int r   = idx >> 4;
        int c4  = idx & 15;
        int row = row0 + r;
        float4 v = make_float4(0.f, 0.f, 0.f, 0.f);
        if (row < n) v = X4[row * 16 + c4];
        int c = c4 << 2;
        XsT[swidx(c + 0, r)] = v.x;
        XsT[swidx(c + 1, r)] = v.y;
        XsT[swidx(c + 2, r)] = v.z;
        XsT[swidx(c + 3, r)] = v.w;
    }
    __syncthreads();

    // 4x4 register tile: thread (tr, tc) owns rows 4tr..4tr+3, cols 4tc..4tc+3.
    const int tc = tid & 15;
    const int tr = tid >> 4;

    // acc2[2c+p]: column (4tc+c), row-pair p (p=0 -> rows 4tr+0/1, p=1 -> +2/3)
    unsigned long long acc2[8];
#pragma unroll
    for (int p = 0; p < 8; ++p) acc2[p] = 0ull;

#pragma unroll 8
    for (int k = 0; k < 64; ++k) {
        int sw = (k >> 2) & 15;
        // A: rows 4tr..4tr+3 at column k, pre-packed as two f32x2 pairs.
        ulonglong2 a = ((const ulonglong2*)(XsT + (k << 6)))[tr ^ sw];
        // W: cols 4tc..4tc+3 at row k.
        float4 wv = ((const float4*)(Ws + (k << 6)))[tc];

        unsigned long long w0 = dup2(wv.x);
        unsigned long long w1 = dup2(wv.y);
        unsigned long long w2 = dup2(wv.z);
        unsigned long long w3 = dup2(wv.w);

        acc2[0] = fma2(a.x, w0, acc2[0]);  acc2[1] = fma2(a.y, w0, acc2[1]);
        acc2[2] = fma2(a.x, w1, acc2[2]);  acc2[3] = fma2(a.y, w1, acc2[3]);
        acc2[4] = fma2(a.x, w2, acc2[4]);  acc2[5] = fma2(a.y, w2, acc2[5]);
        acc2[6] = fma2(a.x, w3, acc2[6]);  acc2[7] = fma2(a.y, w3, acc2[7]);
    }

    // Unpack acc2 -> f[c][m] (column c, row offset m)
    float f[4][4];
#pragma unroll
    for (int c = 0; c < 4; ++c) {
        asm("mov.b64 {%0, %1}, %2;" : "=f"(f[c][0]), "=f"(f[c][1]) : "l"(acc2[2 * c]));
        asm("mov.b64 {%0, %1}, %2;" : "=f"(f[c][2]), "=f"(f[c][3]) : "l"(acc2[2 * c + 1]));
    }

    const int rbase = row0 + (tr << 2);

    if (MODE == 0) {
        float4* xw4  = (float4*)g_xw;
        float4* agg4 = (float4*)g_agg;
        const float4 z4 = make_float4(0.f, 0.f, 0.f, 0.f);
#pragma unroll
        for (int m = 0; m < 4; ++m) {
            int row = rbase + m;
            if (row < n) {
                float4 v = make_float4(f[0][m], f[1][m], f[2][m], f[3][m]);
                xw4 [(size_t)row * 16 + tc] = v;
                agg4[(size_t)row * 16 + tc] = z4;
            }
        }
    } else {
        const float4* agg4 = (const float4*)g_agg;
        float4*       Y4   = (float4*)Y;
        float4 br4 = ((const float4*)bias_r)[tc];
        float4 ba4 = ((const float4*)bias_a)[tc];

        // Issue agg loads first for latency overlap.
        float4 ag[4];
#pragma unroll
        for (int m = 0; m < 4; ++m) {
            int row = rbase + m;
            if (row < n) ag[m] = agg4[(size_t)row * 16 + tc];
        }
#pragma unroll
        for (int m = 0; m < 4; ++m) {
            int row = rbase + m;
            if (row < n) {
                float4 v;
                float c0 = ag[m].x + ba4.x; c0 = c0 > 0.f ? c0 : 0.f;
                float c1 = ag[m].y + ba4.y; c1 = c1 > 0.f ? c1 : 0.f;
                float c2 = ag[m].z + ba4.z; c2 = c2 > 0.f ? c2 : 0.f;
                float c3 = ag[m].w + ba4.w; c3 = c3 > 0.f ? c3 : 0.f;
                float r0 = f[0][m] + br4.x; r0 = r0 > 0.f ? r0 : 0.f;
                float r1 = f[1][m] + br4.y; r1 = r1 > 0.f ? r1 : 0.f;
                float r2 = f[2][m] + br4.z; r2 = r2 > 0.f ? r2 : 0.f;
                float r3 = f[3][m] + br4.w; r3 = r3 > 0.f ? r3 : 0.f;
                v.x = c0 + r0; v.y = c1 + r1; v.z = c2 + r2; v.w = c3 + r3;
                Y4[(size_t)row * 16 + tc] = v;
            }
        }
    }
}

// ============================ scatter ============================
// Vectorized 16B float atomic add (sm_90+): 4 fp32 adds per L2 atomic op.
__device__ __forceinline__ void red_add_v4(float4* addr, float4 v) {
    asm volatile("red.global.add.v4.f32 [%0], {%1, %2, %3, %4};"
                 :: "l"(addr), "f"(v.x), "f"(v.y), "f"(v.z), "f"(v.w)
                 : "memory");
}

// One thread per (edge, float4-quad): 16 threads per edge, fully coalesced
// 256B gather per edge, 16B vector red per thread.
__global__ __launch_bounds__(256)
void scatter_k(const int* __restrict__ src, const int* __restrict__ dst)
{
    unsigned gid = blockIdx.x * 256u + threadIdx.x;   // EE*16 = 19.2M exact
    unsigned e = gid >> 4;
    unsigned q = gid & 15;
    int s = __ldg(src + e);
    int d = __ldg(dst + e);
    const float4* xw4 = (const float4*)g_xw;
    float4 v = __ldg(xw4 + (size_t)s * 16 + q);
    red_add_v4(((float4*)g_agg) + (size_t)d * 16 + q, v);
}

// ============================== launch ==============================

extern "C" void kernel_launch(void* const* d_in, const int* in_sizes, int n_in,
                              void* d_out, int out_size)
{
    const float* feats = (const float*)d_in[0];
    const float* W1    = (const float*)d_in[1];
    const float* b1    = (const float*)d_in[2];
    const float* Wr1   = (const float*)d_in[3];
    const float* br1   = (const float*)d_in[4];
    const float* W2    = (const float*)d_in[5];
    const float* b2    = (const float*)d_in[6];
    const float* Wr2   = (const float*)d_in[7];
    const float* br2   = (const float*)d_in[8];
    const int*   src   = (const int*)d_in[9];
    const int*   dst   = (const int*)d_in[10];
    float*       out   = (float*)d_out;

    const int GB = (NN + 63) >> 6;            // 1563 blocks
    const int SB = (EE * 16) / 256;           // 75000 blocks

    // ---- Layer 1 ----
    gemm64_k<0, false, false><<<GB, 256>>>(feats, W1, nullptr, nullptr, nullptr, NN);
    scatter_k<<<SB, 256>>>(src, dst);
    gemm64_k<1, false, true ><<<GB, 256>>>(feats, Wr1, br1, b1, nullptr, NN);

    // ---- Layer 2 ----
    gemm64_k<0, true,  false><<<GB, 256>>>(nullptr, W2, nullptr, nullptr, nullptr, NN);
    scatter_k<<<SB, 256>>>(src, dst);
    gemm64_k<1, true,  false><<<GB, 256>>>(nullptr, Wr2, br2, b2, out, NN);
}